// round 9
// baseline (speedup 1.0000x reference)
#include <cuda_runtime.h>
#include <cstdint>

#define N_NODES 100000
#define N_EDGES 1600000
#define C 128
#define NGRAPH 128
#define OUTC 10
#define BN_EPS 1e-5f

#define TPB 256
#define RPB 64

typedef unsigned long long u64;

// ---------------- scratch (device globals; no allocation) ----------------
__device__ __align__(16) float g_agg [N_NODES * C];
__device__ __align__(16) float g_hpre[N_NODES * C];
__device__ __align__(16) float g_hbuf[N_NODES * C];

__device__ int g_deg   [N_NODES];
__device__ int g_rowst [N_NODES + 1];
__device__ int g_cursor[N_NODES];
__device__ int g_csr   [N_EDGES];

#define SCAN_B 1024
#define SCAN_NBLK ((N_NODES + SCAN_B - 1) / SCAN_B)   // 98
__device__ int g_bsum[SCAN_NBLK];
__device__ int g_boff[SCAN_NBLK];

// interleaved weights: g_Wp[m][k2*128 + c] = pack(W[2k2][c], W[2k2+1][c])
__device__ __align__(16) u64 g_Wp[4][64 * C];

__device__ __align__(16) float g_sum[2 * C];   // layer-indexed BN sums
__device__ __align__(16) float g_sq [2 * C];
__device__ __align__(16) float g_a[C];
__device__ __align__(16) float g_c[C];
__device__ __align__(16) float g_pooled[NGRAPH * C];
__device__ __align__(16) float g_ro1   [NGRAPH * C];

// ---------------- warm-up: force module (.bss) load BEFORE harness main ----
__global__ void warmup_kernel() {
    if (threadIdx.x == 0 && blockIdx.x == 0) {
        g_deg[0] = 0;
        g_agg[0] = 0.f; g_hpre[0] = 0.f; g_hbuf[0] = 0.f;
        g_csr[0] = 0;  g_Wp[0][0] = 0ull;
    }
}
namespace {
struct ModuleWarm {
    ModuleWarm() {
        warmup_kernel<<<1, 32>>>();
        cudaDeviceSynchronize();   // outside kernel_launch: allowed
    }
};
ModuleWarm s_module_warm;
}

// ---------------- packed f32x2 FMA helpers ----------------
__device__ __forceinline__ void ffma2(u64& d, u64 a, u64 b) {
    asm("fma.rn.f32x2 %0, %1, %2, %0;" : "+l"(d) : "l"(a), "l"(b));
}
__device__ __forceinline__ float pairsum(u64 v) {
    unsigned lo, hi;
    asm("mov.b64 {%0, %1}, %2;" : "=r"(lo), "=r"(hi) : "l"(v));
    return __uint_as_float(lo) + __uint_as_float(hi);
}

// ---------------- W interleave (all 4 weight matrices in one kernel) --------
__global__ void winterleave_all_kernel(const float* __restrict__ W0,
                                       const float* __restrict__ W1,
                                       const float* __restrict__ W2,
                                       const float* __restrict__ W3) {
    int idx = blockIdx.x * blockDim.x + threadIdx.x;   // 8192 = 64*128
    if (idx < 64 * C) {
        int k2 = idx >> 7, c = idx & 127;
        const float* Ws[4] = {W0, W1, W2, W3};
        #pragma unroll
        for (int m = 0; m < 4; m++) {
            float a = Ws[m][(2 * k2) * C + c];
            float b = Ws[m][(2 * k2 + 1) * C + c];
            g_Wp[m][idx] = (u64)__float_as_uint(a) | ((u64)__float_as_uint(b) << 32);
        }
    }
}

// ---------------- zero scratch ----------------
__global__ void zero_kernel() {
    int i = blockIdx.x * blockDim.x + threadIdx.x;
    if (i < N_NODES)    g_deg[i] = 0;
    if (i < NGRAPH * C) g_pooled[i] = 0.f;
    if (i < 2 * C) { g_sum[i] = 0.f; g_sq[i] = 0.f; }
}

// ---------------- CSR build (edge_index is int32), int4 vectorized ---------
__global__ void hist_kernel(const int* __restrict__ dst) {
    int e4 = blockIdx.x * blockDim.x + threadIdx.x;
    if (e4 < N_EDGES / 4) {
        int4 d = ((const int4*)dst)[e4];
        if (d.x >= 0 && d.x < N_NODES) atomicAdd(&g_deg[d.x], 1);
        if (d.y >= 0 && d.y < N_NODES) atomicAdd(&g_deg[d.y], 1);
        if (d.z >= 0 && d.z < N_NODES) atomicAdd(&g_deg[d.z], 1);
        if (d.w >= 0 && d.w < N_NODES) atomicAdd(&g_deg[d.w], 1);
    }
}

// -------- parallel 3-phase exclusive scan of g_deg -> g_rowst/g_cursor ------
__global__ void scan1_kernel() {
    __shared__ int buf[2][SCAN_B];
    int b = blockIdx.x, tid = threadIdx.x;
    int idx = b * SCAN_B + tid;
    int v = (idx < N_NODES) ? g_deg[idx] : 0;
    buf[0][tid] = v;
    __syncthreads();
    int cur = 0;
    #pragma unroll
    for (int off = 1; off < SCAN_B; off <<= 1) {
        int nxt = cur ^ 1;
        int t = buf[cur][tid];
        if (tid >= off) t += buf[cur][tid - off];
        buf[nxt][tid] = t;
        cur = nxt;
        __syncthreads();
    }
    int incl = buf[cur][tid];
    if (idx < N_NODES) g_rowst[idx] = incl - v;     // block-local exclusive
    if (tid == SCAN_B - 1) g_bsum[b] = incl;
}

__global__ void scan2_kernel() {
    if (threadIdx.x == 0) {
        int run = 0;
        for (int i = 0; i < SCAN_NBLK; i++) { g_boff[i] = run; run += g_bsum[i]; }
        g_rowst[N_NODES] = run;
    }
}

__global__ void scan3_kernel() {
    int idx = blockIdx.x * blockDim.x + threadIdx.x;
    if (idx < N_NODES) {
        int r = g_rowst[idx] + g_boff[idx >> 10];
        g_rowst[idx]  = r;
        g_cursor[idx] = r;
    }
}

__global__ void scatter_kernel(const int* __restrict__ src,
                               const int* __restrict__ dst) {
    int e4 = blockIdx.x * blockDim.x + threadIdx.x;
    if (e4 < N_EDGES / 4) {
        int4 d = ((const int4*)dst)[e4];
        int4 s = ((const int4*)src)[e4];
        if (d.x >= 0 && d.x < N_NODES && s.x >= 0 && s.x < N_NODES)
            g_csr[atomicAdd(&g_cursor[d.x], 1)] = s.x;
        if (d.y >= 0 && d.y < N_NODES && s.y >= 0 && s.y < N_NODES)
            g_csr[atomicAdd(&g_cursor[d.y], 1)] = s.y;
        if (d.z >= 0 && d.z < N_NODES && s.z >= 0 && s.z < N_NODES)
            g_csr[atomicAdd(&g_cursor[d.z], 1)] = s.z;
        if (d.w >= 0 && d.w < N_NODES && s.w >= 0 && s.w < N_NODES)
            g_csr[atomicAdd(&g_cursor[d.w], 1)] = s.w;
    }
}

// --------- aggregation: g_agg[i] = x[i] + sum_{j in N(i)} x[j] ----------
// One warp per node; float4 lanes cover 128 channels. High occupancy hides
// gather latency (lesson from round 7: keep this OUT of the GEMM kernel).
#define ATPB 512
__global__ void agg_from_x_kernel(const float* __restrict__ xin) {
    int warp = blockIdx.x * (ATPB / 32) + (threadIdx.x >> 5);
    int lane = threadIdx.x & 31;
    if (warp >= N_NODES) return;
    const float4* x4 = (const float4*)xin;
    float4 acc = x4[warp * 32 + lane];
    int s = g_rowst[warp], e = g_rowst[warp + 1];
    for (int i = s; i < e; i++) {
        int j = g_csr[i];
        float4 v = x4[j * 32 + lane];
        acc.x += v.x; acc.y += v.y; acc.z += v.z; acc.w += v.w;
    }
    ((float4*)g_agg)[warp * 32 + lane] = acc;
}

__global__ void agg_from_h_kernel() {
    int warp = blockIdx.x * (ATPB / 32) + (threadIdx.x >> 5);
    int lane = threadIdx.x & 31;
    if (warp >= N_NODES) return;
    const float4* x4 = (const float4*)g_hbuf;
    float4 acc = x4[warp * 32 + lane];
    int s = g_rowst[warp], e = g_rowst[warp + 1];
    for (int i = s; i < e; i++) {
        int j = g_csr[i];
        float4 v = x4[j * 32 + lane];
        acc.x += v.x; acc.y += v.y; acc.z += v.z; acc.w += v.w;
    }
    ((float4*)g_agg)[warp * 32 + lane] = acc;
}

// ---------------- FFMA2 GEMM mainloop -----------------------------------
// k paired even/odd into f32x2. acc2[i][c] holds (even-k partial, odd-k partial).
__device__ __forceinline__ void gemm_body2(const float* __restrict__ Xs,
                                           const u64* __restrict__ Wp,
                                           int cg, int rg, u64 acc2[8][4]) {
    const u64* Xs2 = (const u64*)Xs;   // [row][k2] pairs, 64 per row
    #pragma unroll 2
    for (int k2 = 0; k2 < 64; k2++) {
        const u64* wrow = Wp + k2 * C + 4 * cg;
        ulonglong2 wab = ((const ulonglong2*)wrow)[0];   // cols 4cg, 4cg+1
        ulonglong2 wcd = ((const ulonglong2*)wrow)[1];   // cols 4cg+2, 4cg+3
        #pragma unroll
        for (int i = 0; i < 8; i++) {
            u64 xp = Xs2[(rg * 8 + i) * 64 + k2];        // LDS.64 broadcast
            ffma2(acc2[i][0], xp, wab.x);
            ffma2(acc2[i][1], xp, wab.y);
            ffma2(acc2[i][2], xp, wcd.x);
            ffma2(acc2[i][3], xp, wcd.y);
        }
    }
}

// ---------------- lin1: g_hpre = g_agg @ W + b, + BN stat accumulation ----------
__global__ void __launch_bounds__(TPB, 2)
lin1_kernel(const float* __restrict__ bias, int layer) {
    __shared__ float Xs[RPB * C];      // 32 KB
    __shared__ float Rs[1024];
    __shared__ float Rq[1024];
    int tid  = threadIdx.x;
    int row0 = blockIdx.x * RPB;

    const float4* X4 = (const float4*)g_agg;
    float4* Xs4 = (float4*)Xs;
    #pragma unroll
    for (int i = 0; i < 8; i++) {
        int idx = i * TPB + tid;
        int r = row0 + (idx >> 5);
        Xs4[idx] = (r < N_NODES) ? X4[r * 32 + (idx & 31)] : make_float4(0.f, 0.f, 0.f, 0.f);
    }
    __syncthreads();

    int cg = tid & 31;
    int rg = tid >> 5;

    u64 acc2[8][4];
    #pragma unroll
    for (int i = 0; i < 8; i++) { acc2[i][0]=0; acc2[i][1]=0; acc2[i][2]=0; acc2[i][3]=0; }

    gemm_body2(Xs, g_Wp[layer * 2], cg, rg, acc2);

    float4 bv = ((const float4*)bias)[cg];
    float s[4] = {0,0,0,0}, q[4] = {0,0,0,0};
    #pragma unroll
    for (int i = 0; i < 8; i++) {
        int r = row0 + rg * 8 + i;
        if (r < N_NODES) {
            float4 y;
            y.x = pairsum(acc2[i][0]) + bv.x;
            y.y = pairsum(acc2[i][1]) + bv.y;
            y.z = pairsum(acc2[i][2]) + bv.z;
            y.w = pairsum(acc2[i][3]) + bv.w;
            ((float4*)g_hpre)[r * 32 + cg] = y;
            s[0] += y.x; q[0] += y.x * y.x;
            s[1] += y.y; q[1] += y.y * y.y;
            s[2] += y.z; q[2] += y.z * y.z;
            s[3] += y.w; q[3] += y.w * y.w;
        }
    }
    #pragma unroll
    for (int j = 0; j < 4; j++) {
        Rs[(rg * 32 + cg) * 4 + j] = s[j];
        Rq[(rg * 32 + cg) * 4 + j] = q[j];
    }
    __syncthreads();
    if (rg == 0) {
        #pragma unroll
        for (int j = 0; j < 4; j++) {
            float ts = 0.f, tq = 0.f;
            #pragma unroll
            for (int g = 0; g < 8; g++) {
                ts += Rs[(g * 32 + cg) * 4 + j];
                tq += Rq[(g * 32 + cg) * 4 + j];
            }
            atomicAdd(&g_sum[layer * C + cg * 4 + j], ts);
            atomicAdd(&g_sq [layer * C + cg * 4 + j], tq);
        }
    }
}

// ---------------- BN coefficients ----------------
__global__ void bncoef_kernel(const float* __restrict__ gamma, const float* __restrict__ beta,
                              int layer) {
    int i = threadIdx.x;
    float sm = g_sum[layer * C + i];
    float sq = g_sq [layer * C + i];
    float m = sm / (float)N_NODES;
    float v = sq / (float)N_NODES - m * m;
    float a = gamma[i] * rsqrtf(v + BN_EPS);
    g_a[i] = a;
    g_c[i] = beta[i] - m * a;
}

// ---------------- lin2: g_hbuf = relu( relu(g_hpre*a+c) @ W + b ) ----------------
__global__ void __launch_bounds__(TPB, 2)
lin2_kernel(const float* __restrict__ bias, int layer) {
    __shared__ float Xs[RPB * C];   // 32 KB
    int tid  = threadIdx.x;
    int row0 = blockIdx.x * RPB;

    const float4* X4 = (const float4*)g_hpre;
    const float4* A4 = (const float4*)g_a;
    const float4* C4 = (const float4*)g_c;
    float4* Xs4 = (float4*)Xs;
    #pragma unroll
    for (int i = 0; i < 8; i++) {
        int idx = i * TPB + tid;
        int r  = row0 + (idx >> 5);
        int kc = idx & 31;
        float4 v = (r < N_NODES) ? X4[r * 32 + kc] : make_float4(0.f, 0.f, 0.f, 0.f);
        float4 av = A4[kc], cv = C4[kc];
        v.x = fmaxf(v.x * av.x + cv.x, 0.f);
        v.y = fmaxf(v.y * av.y + cv.y, 0.f);
        v.z = fmaxf(v.z * av.z + cv.z, 0.f);
        v.w = fmaxf(v.w * av.w + cv.w, 0.f);
        Xs4[idx] = v;
    }
    __syncthreads();

    int cg = tid & 31;
    int rg = tid >> 5;

    u64 acc2[8][4];
    #pragma unroll
    for (int i = 0; i < 8; i++) { acc2[i][0]=0; acc2[i][1]=0; acc2[i][2]=0; acc2[i][3]=0; }

    gemm_body2(Xs, g_Wp[layer * 2 + 1], cg, rg, acc2);

    float4 bv = ((const float4*)bias)[cg];
    #pragma unroll
    for (int i = 0; i < 8; i++) {
        int r = row0 + rg * 8 + i;
        if (r < N_NODES) {
            float4 y;
            y.x = fmaxf(pairsum(acc2[i][0]) + bv.x, 0.f);
            y.y = fmaxf(pairsum(acc2[i][1]) + bv.y, 0.f);
            y.z = fmaxf(pairsum(acc2[i][2]) + bv.z, 0.f);
            y.w = fmaxf(pairsum(acc2[i][3]) + bv.w, 0.f);
            ((float4*)g_hbuf)[r * 32 + cg] = y;
        }
    }
}

// ---------------- pooling: batch sorted -> run-accumulate, flush on change ------
#define POOL_BLOCKS 512
__global__ void pool_kernel(const int* __restrict__ batch) {
    int per = (N_NODES + POOL_BLOCKS - 1) / POOL_BLOCKS;
    int lo = blockIdx.x * per;
    int hi = lo + per; if (hi > N_NODES) hi = N_NODES;
    if (lo >= hi) return;
    int t = threadIdx.x;   // channel
    int cur = batch[lo];
    float acc = 0.f;
    for (int r = lo; r < hi; r++) {
        int b = batch[r];
        if (b != cur) {
            if (cur >= 0 && cur < NGRAPH) atomicAdd(&g_pooled[cur * C + t], acc);
            acc = 0.f; cur = b;
        }
        acc += g_hbuf[r * C + t];
    }
    if (cur >= 0 && cur < NGRAPH) atomicAdd(&g_pooled[cur * C + t], acc);
}

// ---------------- readout ----------------
__global__ void ro1_kernel(const float* __restrict__ W, const float* __restrict__ b) {
    __shared__ float row[C];
    int g = blockIdx.x, t = threadIdx.x;
    row[t] = g_pooled[g * C + t];
    __syncthreads();
    float acc = b[t];
    #pragma unroll 8
    for (int k = 0; k < C; k++) acc += row[k] * W[k * C + t];
    g_ro1[g * C + t] = fmaxf(acc, 0.f);
}

__global__ void ro2_kernel(const float* __restrict__ W, const float* __restrict__ b,
                           float* __restrict__ out) {
    __shared__ float row[C];
    int g = blockIdx.x, t = threadIdx.x;
    row[t] = g_ro1[g * C + t];
    __syncthreads();
    if (t < OUTC) {
        float acc = b[t];
        #pragma unroll 8
        for (int k = 0; k < C; k++) acc += row[k] * W[k * OUTC + t];
        out[g * OUTC + t] = acc;
    }
}

// ---------------- launch ----------------
extern "C" void kernel_launch(void* const* d_in, const int* in_sizes, int n_in,
                              void* d_out, int out_size) {
    const float* x     = (const float*)d_in[0];
    const int*   ei    = (const int*)d_in[1];     // int32: JAX x64 disabled
    const int*   batch = (const int*)d_in[2];     // int32
    const float *W1a=(const float*)d_in[3],  *b1a=(const float*)d_in[4];
    const float *ga =(const float*)d_in[5],  *ba =(const float*)d_in[6];
    const float *W2a=(const float*)d_in[7],  *b2a=(const float*)d_in[8];
    const float *W1b=(const float*)d_in[9],  *b1b=(const float*)d_in[10];
    const float *gb =(const float*)d_in[11], *bb =(const float*)d_in[12];
    const float *W2b=(const float*)d_in[13], *b2b=(const float*)d_in[14];
    const float *Wl1=(const float*)d_in[15], *bl1=(const float*)d_in[16];
    const float *Wl2=(const float*)d_in[17], *bl2=(const float*)d_in[18];
    float* out = (float*)d_out;

    const int* src = ei;
    const int* dst = ei + N_EDGES;

    int zgrid  = (N_NODES + 255) / 256;
    int e4grid = (N_EDGES / 4 + 255) / 256;
    int agrid  = (N_NODES + (ATPB / 32) - 1) / (ATPB / 32);  // one warp per node
    int ggrid  = (N_NODES + RPB - 1) / RPB;
    int wgrid  = (64 * C + 255) / 256;

    zero_kernel<<<zgrid, 256>>>();
    winterleave_all_kernel<<<wgrid, 256>>>(W1a, W2a, W1b, W2b);
    hist_kernel<<<e4grid, 256>>>(dst);
    scan1_kernel<<<SCAN_NBLK, SCAN_B>>>();
    scan2_kernel<<<1, 32>>>();
    scan3_kernel<<<zgrid, 256>>>();
    scatter_kernel<<<e4grid, 256>>>(src, dst);

    // ---- layer 1 ----
    agg_from_x_kernel<<<agrid, ATPB>>>(x);
    lin1_kernel<<<ggrid, TPB>>>(b1a, 0);
    bncoef_kernel<<<1, C>>>(ga, ba, 0);
    lin2_kernel<<<ggrid, TPB>>>(b2a, 0);

    // ---- layer 2 ----
    agg_from_h_kernel<<<agrid, ATPB>>>();
    lin1_kernel<<<ggrid, TPB>>>(b1b, 1);
    bncoef_kernel<<<1, C>>>(gb, bb, 1);
    lin2_kernel<<<ggrid, TPB>>>(b2b, 1);

    // ---- pooling + readout ----
    pool_kernel<<<POOL_BLOCKS, C>>>(batch);
    ro1_kernel<<<NGRAPH, C>>>(Wl1, bl1);
    ro2_kernel<<<NGRAPH, C>>>(Wl2, bl2, out);
}

// round 11
// speedup vs baseline: 1.2218x; 1.2218x over previous
#include <cuda_runtime.h>
#include <cuda_bf16.h>
#include <cstdint>

#define N_NODES 100000
#define N_EDGES 1600000
#define C 128
#define NGRAPH 128
#define OUTC 10
#define BN_EPS 1e-5f

typedef unsigned long long u64;
typedef unsigned int u32;

// ---------------- scratch (device globals; no allocation) ----------------
__device__ __align__(16) float g_agg [N_NODES * C];
__device__ __align__(16) float g_hpre[N_NODES * C];
__device__ __align__(16) float g_hbuf[N_NODES * C];

__device__ int g_deg   [N_NODES];
__device__ int g_rowst [N_NODES + 1];
__device__ int g_cursor[N_NODES];
__device__ int g_csr   [N_EDGES];

#define SCAN_B 1024
#define SCAN_NBLK ((N_NODES + SCAN_B - 1) / SCAN_B)   // 98
__device__ int g_bsum[SCAN_NBLK];
__device__ int g_boff[SCAN_NBLK];

// W^T bf16 hi/lo images, padded rows: [matrix][hi/lo][128 rows * 68 words]
#define WROW_W 68     // words per padded row (136 bf16 = 272 B)
#define WIMG_W (128 * WROW_W)   // 8704 u32
__device__ __align__(16) u32 g_Wimg[4][2][WIMG_W];

__device__ __align__(16) float g_sum[2 * C];
__device__ __align__(16) float g_sq [2 * C];
__device__ __align__(16) float g_a[C];
__device__ __align__(16) float g_c[C];
__device__ __align__(16) float g_pooled[NGRAPH * C];
__device__ __align__(16) float g_ro1   [NGRAPH * C];

// smem layout: XH, XL, WH, WL each 128*68 u32 = 34816 B
#define SM_XH 0
#define SM_XL 34816
#define SM_WH 69632
#define SM_WL 104448
#define SM_TOTAL 139264

// ---------------- warm-up: force module (.bss) load BEFORE harness main ----
__global__ void warmup_kernel() {
    if (threadIdx.x == 0 && blockIdx.x == 0) {
        g_deg[0] = 0;
        g_agg[0] = 0.f; g_hpre[0] = 0.f; g_hbuf[0] = 0.f;
        g_csr[0] = 0;  g_Wimg[0][0][0] = 0u;
    }
}
__global__ void lin_mma_kernel(const float*, int, int);
namespace {
struct ModuleWarm {
    ModuleWarm() {
        warmup_kernel<<<1, 32>>>();
        cudaFuncSetAttribute(lin_mma_kernel, cudaFuncAttributeMaxDynamicSharedMemorySize,
                             SM_TOTAL);
        cudaDeviceSynchronize();   // outside kernel_launch: allowed
    }
};
ModuleWarm s_module_warm;
}

// ---------------- bf16 split + mma.sync helpers ----------------------------
__device__ __forceinline__ void bf16_split(float x, unsigned short& h, unsigned short& l) {
    __nv_bfloat16 hb = __float2bfloat16_rn(x);
    __nv_bfloat16 lb = __float2bfloat16_rn(x - __bfloat162float(hb));
    h = __bfloat16_as_ushort(hb);
    l = __bfloat16_as_ushort(lb);
}
__device__ __forceinline__ void mma16816(float c[4], const u32 a[4], u32 b0, u32 b1) {
    asm volatile(
        "mma.sync.aligned.m16n8k16.row.col.f32.bf16.bf16.f32 "
        "{%0,%1,%2,%3}, {%4,%5,%6,%7}, {%8,%9}, {%0,%1,%2,%3};"
        : "+f"(c[0]), "+f"(c[1]), "+f"(c[2]), "+f"(c[3])
        : "r"(a[0]), "r"(a[1]), "r"(a[2]), "r"(a[3]), "r"(b0), "r"(b1));
}

// ---------------- zero scratch ----------------
__global__ void zero_kernel() {
    int i = blockIdx.x * blockDim.x + threadIdx.x;
    if (i < N_NODES)    g_deg[i] = 0;
    if (i < NGRAPH * C) g_pooled[i] = 0.f;
    if (i < 2 * C) { g_sum[i] = 0.f; g_sq[i] = 0.f; }
}

// ---- W split prep: W^T (row n = output col, k-major), bf16 hi/lo, padded ---
__global__ void wsplit_kernel(const float* __restrict__ W0, const float* __restrict__ W1,
                              const float* __restrict__ W2, const float* __restrict__ W3) {
    int idx = blockIdx.x * blockDim.x + threadIdx.x;   // 8192
    if (idx >= 8192) return;
    int n = idx >> 6, kp = idx & 63, k = kp << 1;
    int word = n * WROW_W + kp;
    const float* Ws[4] = {W0, W1, W2, W3};
    #pragma unroll
    for (int m = 0; m < 4; m++) {
        unsigned short h0, l0, h1, l1;
        bf16_split(Ws[m][k * C + n], h0, l0);
        bf16_split(Ws[m][(k + 1) * C + n], h1, l1);
        g_Wimg[m][0][word] = (u32)h0 | ((u32)h1 << 16);
        g_Wimg[m][1][word] = (u32)l0 | ((u32)l1 << 16);
    }
}

// ---------------- CSR build (edge_index int32), int4 vectorized -------------
__global__ void hist_kernel(const int* __restrict__ dst) {
    int e4 = blockIdx.x * blockDim.x + threadIdx.x;
    if (e4 < N_EDGES / 4) {
        int4 d = ((const int4*)dst)[e4];
        if (d.x >= 0 && d.x < N_NODES) atomicAdd(&g_deg[d.x], 1);
        if (d.y >= 0 && d.y < N_NODES) atomicAdd(&g_deg[d.y], 1);
        if (d.z >= 0 && d.z < N_NODES) atomicAdd(&g_deg[d.z], 1);
        if (d.w >= 0 && d.w < N_NODES) atomicAdd(&g_deg[d.w], 1);
    }
}

__global__ void scan1_kernel() {
    __shared__ int buf[2][SCAN_B];
    int b = blockIdx.x, tid = threadIdx.x;
    int idx = b * SCAN_B + tid;
    int v = (idx < N_NODES) ? g_deg[idx] : 0;
    buf[0][tid] = v;
    __syncthreads();
    int cur = 0;
    #pragma unroll
    for (int off = 1; off < SCAN_B; off <<= 1) {
        int nxt = cur ^ 1;
        int t = buf[cur][tid];
        if (tid >= off) t += buf[cur][tid - off];
        buf[nxt][tid] = t;
        cur = nxt;
        __syncthreads();
    }
    int incl = buf[cur][tid];
    if (idx < N_NODES) g_rowst[idx] = incl - v;
    if (tid == SCAN_B - 1) g_bsum[b] = incl;
}

__global__ void scan2_kernel() {
    if (threadIdx.x == 0) {
        int run = 0;
        for (int i = 0; i < SCAN_NBLK; i++) { g_boff[i] = run; run += g_bsum[i]; }
        g_rowst[N_NODES] = run;
    }
}

__global__ void scan3_kernel() {
    int idx = blockIdx.x * blockDim.x + threadIdx.x;
    if (idx < N_NODES) {
        int r = g_rowst[idx] + g_boff[idx >> 10];
        g_rowst[idx]  = r;
        g_cursor[idx] = r;
    }
}

__global__ void scatter_kernel(const int* __restrict__ src,
                               const int* __restrict__ dst) {
    int e4 = blockIdx.x * blockDim.x + threadIdx.x;
    if (e4 < N_EDGES / 4) {
        int4 d = ((const int4*)dst)[e4];
        int4 s = ((const int4*)src)[e4];
        if (d.x >= 0 && d.x < N_NODES && s.x >= 0 && s.x < N_NODES)
            g_csr[atomicAdd(&g_cursor[d.x], 1)] = s.x;
        if (d.y >= 0 && d.y < N_NODES && s.y >= 0 && s.y < N_NODES)
            g_csr[atomicAdd(&g_cursor[d.y], 1)] = s.y;
        if (d.z >= 0 && d.z < N_NODES && s.z >= 0 && s.z < N_NODES)
            g_csr[atomicAdd(&g_cursor[d.z], 1)] = s.z;
        if (d.w >= 0 && d.w < N_NODES && s.w >= 0 && s.w < N_NODES)
            g_csr[atomicAdd(&g_cursor[d.w], 1)] = s.w;
    }
}

// --------- aggregation: g_agg[i] = x[i] + sum_{j in N(i)} x[j] ----------
#define ATPB 512
__global__ void agg_from_x_kernel(const float* __restrict__ xin) {
    int warp = blockIdx.x * (ATPB / 32) + (threadIdx.x >> 5);
    int lane = threadIdx.x & 31;
    if (warp >= N_NODES) return;
    const float4* x4 = (const float4*)xin;
    float4 acc = x4[warp * 32 + lane];
    int s = g_rowst[warp], e = g_rowst[warp + 1];
    for (int i = s; i < e; i++) {
        int j = g_csr[i];
        float4 v = x4[j * 32 + lane];
        acc.x += v.x; acc.y += v.y; acc.z += v.z; acc.w += v.w;
    }
    ((float4*)g_agg)[warp * 32 + lane] = acc;
}

__global__ void agg_from_h_kernel() {
    int warp = blockIdx.x * (ATPB / 32) + (threadIdx.x >> 5);
    int lane = threadIdx.x & 31;
    if (warp >= N_NODES) return;
    const float4* x4 = (const float4*)g_hbuf;
    float4 acc = x4[warp * 32 + lane];
    int s = g_rowst[warp], e = g_rowst[warp + 1];
    for (int i = s; i < e; i++) {
        int j = g_csr[i];
        float4 v = x4[j * 32 + lane];
        acc.x += v.x; acc.y += v.y; acc.z += v.z; acc.w += v.w;
    }
    ((float4*)g_agg)[warp * 32 + lane] = acc;
}

// ---------------- mma.sync bf16-split GEMM: 128-row tile x 128 cols ---------
// mode 0: g_hpre = g_agg @ W + b
// mode 1: g_hbuf = relu(relu(g_hpre*a+c) @ W + b)
// 3 accumulating passes: Ah*Bh + Ah*Bl + Al*Bh  (2-way bf16 split ~ fp32)
// Warp wid: rows (wid&3)*32..+31, cols (wid>>2)*64..+63.
__global__ void __launch_bounds__(256, 1)
lin_mma_kernel(const float* __restrict__ bias, int m, int mode) {
    extern __shared__ char smem[];
    u32* XH = (u32*)(smem + SM_XH);
    u32* XL = (u32*)(smem + SM_XL);
    u32* WH = (u32*)(smem + SM_WH);
    u32* WL = (u32*)(smem + SM_WL);
    int tid = threadIdx.x, lane = tid & 31, wid = tid >> 5;
    int row0 = blockIdx.x * 128;

    // ---- convert X tile -> bf16 hi/lo (padded rows, conflict-free) ----
    const float2* s2 = mode ? (const float2*)g_hpre : (const float2*)g_agg;
    #pragma unroll 4
    for (int i = 0; i < 32; i++) {
        int idx = tid + i * 256;          // 0..8191
        int row = idx >> 6, kp = idx & 63;
        int r = row0 + row;
        float2 v = make_float2(0.f, 0.f);
        if (r < N_NODES) v = s2[r * 64 + kp];
        if (mode) {
            float2 av = ((const float2*)g_a)[kp];
            float2 cv = ((const float2*)g_c)[kp];
            v.x = fmaxf(v.x * av.x + cv.x, 0.f);
            v.y = fmaxf(v.y * av.y + cv.y, 0.f);
        }
        unsigned short h0, l0, h1, l1;
        bf16_split(v.x, h0, l0);
        bf16_split(v.y, h1, l1);
        int word = row * WROW_W + kp;
        XH[word] = (u32)h0 | ((u32)h1 << 16);
        XL[word] = (u32)l0 | ((u32)l1 << 16);
    }
    // ---- copy W^T images (8704 u32 = 2176 float4 per half) ----
    {
        const float4* wh4 = (const float4*)g_Wimg[m][0];
        const float4* wl4 = (const float4*)g_Wimg[m][1];
        float4* dh = (float4*)WH;
        float4* dl = (float4*)WL;
        #pragma unroll
        for (int i = 0; i < 9; i++) {
            int p = tid + i * 256;
            if (p < WIMG_W / 4) { dh[p] = wh4[p]; dl[p] = wl4[p]; }
        }
    }
    __syncthreads();

    int wr0 = (wid & 3) * 32;
    int wc0 = (wid >> 2) * 64;
    int grp = lane >> 2, tg = lane & 3;

    float acc[2][8][4];
    #pragma unroll
    for (int mt = 0; mt < 2; mt++)
        #pragma unroll
        for (int nt = 0; nt < 8; nt++)
            #pragma unroll
            for (int j = 0; j < 4; j++) acc[mt][nt][j] = 0.f;

    for (int pass = 0; pass < 3; pass++) {
        const u32* Aw = (pass == 2) ? XL : XH;
        const u32* Bw = (pass == 1) ? WL : WH;
        #pragma unroll 2
        for (int ks = 0; ks < 8; ks++) {
            int k0w = ks * 8 + tg;             // word offset of k0 within row
            u32 a[2][4];
            #pragma unroll
            for (int mt = 0; mt < 2; mt++) {
                int r = wr0 + mt * 16 + grp;
                a[mt][0] = Aw[r * WROW_W + k0w];
                a[mt][1] = Aw[(r + 8) * WROW_W + k0w];
                a[mt][2] = Aw[r * WROW_W + k0w + 4];
                a[mt][3] = Aw[(r + 8) * WROW_W + k0w + 4];
            }
            #pragma unroll
            for (int nt = 0; nt < 8; nt++) {
                int n = wc0 + nt * 8 + grp;
                u32 b0 = Bw[n * WROW_W + k0w];
                u32 b1 = Bw[n * WROW_W + k0w + 4];
                mma16816(acc[0][nt], a[0], b0, b1);
                mma16816(acc[1][nt], a[1], b0, b1);
            }
        }
    }

    // ---- epilogue ----
    float* dst = mode ? g_hbuf : g_hpre;
    #pragma unroll
    for (int nt = 0; nt < 8; nt++) {
        int col = wc0 + nt * 8 + tg * 2;
        float2 bb = *(const float2*)(bias + col);
        #pragma unroll
        for (int mt = 0; mt < 2; mt++) {
            int r0 = row0 + wr0 + mt * 16 + grp;
            if (r0 < N_NODES) {
                float2 y;
                y.x = acc[mt][nt][0] + bb.x;
                y.y = acc[mt][nt][1] + bb.y;
                if (mode) { y.x = fmaxf(y.x, 0.f); y.y = fmaxf(y.y, 0.f); }
                *(float2*)(dst + r0 * C + col) = y;
            }
            int r1 = r0 + 8;
            if (r1 < N_NODES) {
                float2 y;
                y.x = acc[mt][nt][2] + bb.x;
                y.y = acc[mt][nt][3] + bb.y;
                if (mode) { y.x = fmaxf(y.x, 0.f); y.y = fmaxf(y.y, 0.f); }
                *(float2*)(dst + r1 * C + col) = y;
            }
        }
    }
}

// ---------------- BN stats over g_hpre (separate cheap pass) ---------------
#define BN_BLOCKS 296
__global__ void bnstat_kernel(int layer) {
    __shared__ float shs[256], shq[256];
    int chunk = (N_NODES + BN_BLOCKS - 1) / BN_BLOCKS;
    int lo = blockIdx.x * chunk;
    int hi = lo + chunk; if (hi > N_NODES) hi = N_NODES;
    int col = threadIdx.x & 127, half = threadIdx.x >> 7;
    float s = 0.f, q = 0.f;
    for (int r = lo + half; r < hi; r += 2) {
        float v = g_hpre[r * C + col];
        s += v; q += v * v;
    }
    shs[threadIdx.x] = s; shq[threadIdx.x] = q;
    __syncthreads();
    if (half == 0) {
        atomicAdd(&g_sum[layer * C + col], s + shs[128 + col]);
        atomicAdd(&g_sq [layer * C + col], q + shq[128 + col]);
    }
}

__global__ void bncoef_kernel(const float* __restrict__ gamma, const float* __restrict__ beta,
                              int layer) {
    int i = threadIdx.x;
    float sm = g_sum[layer * C + i];
    float sq = g_sq [layer * C + i];
    float m = sm / (float)N_NODES;
    float v = sq / (float)N_NODES - m * m;
    float a = gamma[i] * rsqrtf(v + BN_EPS);
    g_a[i] = a;
    g_c[i] = beta[i] - m * a;
}

// ---------------- pooling: batch sorted -> run-accumulate ------------------
#define POOL_BLOCKS 512
__global__ void pool_kernel(const int* __restrict__ batch) {
    int per = (N_NODES + POOL_BLOCKS - 1) / POOL_BLOCKS;
    int lo = blockIdx.x * per;
    int hi = lo + per; if (hi > N_NODES) hi = N_NODES;
    if (lo >= hi) return;
    int t = threadIdx.x;
    int cur = batch[lo];
    float acc = 0.f;
    for (int r = lo; r < hi; r++) {
        int b = batch[r];
        if (b != cur) {
            if (cur >= 0 && cur < NGRAPH) atomicAdd(&g_pooled[cur * C + t], acc);
            acc = 0.f; cur = b;
        }
        acc += g_hbuf[r * C + t];
    }
    if (cur >= 0 && cur < NGRAPH) atomicAdd(&g_pooled[cur * C + t], acc);
}

// ---------------- readout ----------------
__global__ void ro1_kernel(const float* __restrict__ W, const float* __restrict__ b) {
    __shared__ float row[C];
    int g = blockIdx.x, t = threadIdx.x;
    row[t] = g_pooled[g * C + t];
    __syncthreads();
    float acc = b[t];
    #pragma unroll 8
    for (int k = 0; k < C; k++) acc += row[k] * W[k * C + t];
    g_ro1[g * C + t] = fmaxf(acc, 0.f);
}

__global__ void ro2_kernel(const float* __restrict__ W, const float* __restrict__ b,
                           float* __restrict__ out) {
    __shared__ float row[C];
    int g = blockIdx.x, t = threadIdx.x;
    row[t] = g_ro1[g * C + t];
    __syncthreads();
    if (t < OUTC) {
        float acc = b[t];
        #pragma unroll 8
        for (int k = 0; k < C; k++) acc += row[k] * W[k * OUTC + t];
        out[g * OUTC + t] = acc;
    }
}

// ---------------- launch ----------------
extern "C" void kernel_launch(void* const* d_in, const int* in_sizes, int n_in,
                              void* d_out, int out_size) {
    const float* x     = (const float*)d_in[0];
    const int*   ei    = (const int*)d_in[1];     // int32: JAX x64 disabled
    const int*   batch = (const int*)d_in[2];     // int32
    const float *W1a=(const float*)d_in[3],  *b1a=(const float*)d_in[4];
    const float *ga =(const float*)d_in[5],  *ba =(const float*)d_in[6];
    const float *W2a=(const float*)d_in[7],  *b2a=(const float*)d_in[8];
    const float *W1b=(const float*)d_in[9],  *b1b=(const float*)d_in[10];
    const float *gb =(const float*)d_in[11], *bb =(const float*)d_in[12];
    const float *W2b=(const float*)d_in[13], *b2b=(const float*)d_in[14];
    const float *Wl1=(const float*)d_in[15], *bl1=(const float*)d_in[16];
    const float *Wl2=(const float*)d_in[17], *bl2=(const float*)d_in[18];
    float* out = (float*)d_out;

    const int* src = ei;
    const int* dst = ei + N_EDGES;

    int zgrid  = (N_NODES + 255) / 256;
    int e4grid = (N_EDGES / 4 + 255) / 256;
    int agrid  = (N_NODES + (ATPB / 32) - 1) / (ATPB / 32);
    int tcgrid = (N_NODES + 127) / 128;      // 782

    zero_kernel<<<zgrid, 256>>>();
    wsplit_kernel<<<32, 256>>>(W1a, W2a, W1b, W2b);
    hist_kernel<<<e4grid, 256>>>(dst);
    scan1_kernel<<<SCAN_NBLK, SCAN_B>>>();
    scan2_kernel<<<1, 32>>>();
    scan3_kernel<<<zgrid, 256>>>();
    scatter_kernel<<<e4grid, 256>>>(src, dst);

    // ---- layer 1 ----
    agg_from_x_kernel<<<agrid, ATPB>>>(x);
    lin_mma_kernel<<<tcgrid, 256, SM_TOTAL>>>(b1a, 0, 0);
    bnstat_kernel<<<BN_BLOCKS, 256>>>(0);
    bncoef_kernel<<<1, C>>>(ga, ba, 0);
    lin_mma_kernel<<<tcgrid, 256, SM_TOTAL>>>(b2a, 1, 1);

    // ---- layer 2 ----
    agg_from_h_kernel<<<agrid, ATPB>>>();
    lin_mma_kernel<<<tcgrid, 256, SM_TOTAL>>>(b1b, 2, 0);
    bnstat_kernel<<<BN_BLOCKS, 256>>>(1);
    bncoef_kernel<<<1, C>>>(gb, bb, 1);
    lin_mma_kernel<<<tcgrid, 256, SM_TOTAL>>>(b2b, 3, 1);

    // ---- pooling + readout ----
    pool_kernel<<<POOL_BLOCKS, C>>>(batch);
    ro1_kernel<<<NGRAPH, C>>>(Wl1, bl1);
    ro2_kernel<<<NGRAPH, C>>>(Wl2, bl2, out);
}